// round 16
// baseline (speedup 1.0000x reference)
#include <cuda_runtime.h>
#include <math.h>
#include <stdint.h>

// MoE router: logits = x @ W^T  ([16384,2048] x [2048,8]), top-2 + softmax.
// Output layout (fp32): [indices 16384*2][gates 16384*2][logits 16384*8].
//
// R15 base (continuous cross-group cp.async pipeline; W in smem; tree
// reduction epilogue) + expert-pair FFMA2:
//   - W stored interleaved ws2[d*8+e] so one fma.rn.f32x2 covers an expert
//     PAIR: 64 FFMA2 + 16 dups replace 128 scalar FFMA per chunk. At full
//     HBM the FMA pipe now needs ~48% of its cap instead of ~97%.
//   - 16B-slot XOR swizzle (slot ^= lane&7) makes the interleaved W reads
//     bank-conflict-free (structural minimum phases).

#define DDIM 2048
#define NEXP 8
#define TGRP 4
#define CHUNKS (DDIM / 128)        // 16 chunks of 128 floats (4 per lane)
#define W_FLOATS (NEXP * DDIM)     // 16384
#define NWARP 16
#define THREADS (NWARP * 32)
#define NSTAGE 4
#define STAGE_FLOATS (TGRP * 128)  // 512 floats = 2KB
#define XBUF_FLOATS (NWARP * NSTAGE * STAGE_FLOATS)
#define SMEM_BYTES ((W_FLOATS + XBUF_FLOATS) * 4)   // 64KB + 128KB = 192KB
#define NBLOCK 148

typedef unsigned long long u64;

__device__ __forceinline__ void cp_async16(uint32_t dst, const float* src) {
    asm volatile("cp.async.cg.shared.global [%0], [%1], 16;"
                 :: "r"(dst), "l"(src));
}
__device__ __forceinline__ void cp_commit() {
    asm volatile("cp.async.commit_group;");
}
__device__ __forceinline__ void cp_wait3() {
    asm volatile("cp.async.wait_group 3;");
}
// d = a*b + d on both packed f32 halves (sm_103a FFMA2).
__device__ __forceinline__ void ffma2(u64& d, u64 a, u64 b) {
    asm("fma.rn.f32x2 %0, %1, %2, %3;" : "=l"(d) : "l"(a), "l"(b), "l"(d));
}
__device__ __forceinline__ u64 dup2(float v) {
    u64 r;
    asm("mov.b64 %0, {%1, %1};" : "=l"(r) : "f"(v));
    return r;
}

__global__ __launch_bounds__(THREADS, 1)
void router_kernel(const float* __restrict__ x,
                   const float* __restrict__ w,
                   float* __restrict__ out,
                   int n_tokens, int groups_total)
{
    extern __shared__ float smem[];
    float* ws2 = smem;   // interleaved+swizzled W, 16384 floats
    const int lane = threadIdx.x & 31;
    const int wid  = threadIdx.x >> 5;

    // Build interleaved W: logical float index j -> (e = j&7, d = j>>3),
    // 16B slot s = j>>2 swizzled to s ^ ((s>>3)&7).
    for (int j = threadIdx.x; j < W_FLOATS; j += THREADS) {
        const int e = j & 7, d = j >> 3;
        const int s = j >> 2;
        const int sp = s ^ ((s >> 3) & 7);
        ws2[(sp << 2) | (j & 3)] = w[e * DDIM + d];
    }
    __syncthreads();

    float* xbuf = smem + W_FLOATS + wid * (NSTAGE * STAGE_FLOATS);
    const uint32_t xbuf_u32 =
        (uint32_t)__cvta_generic_to_shared(xbuf) + lane * 16;

    // Warp-major group assignment: spreads multi-group warps over all SMs.
    const int gw      = wid * NBLOCK + (int)blockIdx.x;
    const int gstride = NBLOCK * NWARP;
    const int ngroups = (gw < groups_total)
                      ? (groups_total - 1 - gw) / gstride + 1 : 0;

    float* out_idx    = out;
    float* out_gate   = out + (size_t)n_tokens * 2;
    float* out_logits = out + (size_t)n_tokens * 4;

    if (ngroups == 0) return;

    // Pipeline prologue: chunks 0..3 of the first group.
    {
        const float* xp0 = x + (size_t)(gw * TGRP) * DDIM + lane * 4;
        #pragma unroll
        for (int c = 0; c < NSTAGE; c++) {
            #pragma unroll
            for (int t = 0; t < TGRP; t++)
                cp_async16(xbuf_u32 + (c * STAGE_FLOATS + t * 128) * 4,
                           xp0 + (size_t)t * DDIM + c * 128);
            cp_commit();
        }
    }

    const int sw = lane & 7;

    for (int k = 0; k < ngroups; k++) {
        const int g    = gw + k * gstride;
        const int tok0 = g * TGRP;
        const float* xp = x + (size_t)tok0 * DDIM + lane * 4;
        const bool has_next = (k + 1 < ngroups);
        const float* xp_n = has_next
            ? x + (size_t)((g + gstride) * TGRP) * DDIM + lane * 4 : xp;

        // acc[t][ep] = f32x2 (sum expert 2ep, sum expert 2ep+1).
        u64 acc[TGRP][4];
        #pragma unroll
        for (int t = 0; t < TGRP; t++)
            #pragma unroll
            for (int p = 0; p < 4; p++)
                acc[t][p] = 0ull;

        #pragma unroll
        for (int c = 0; c < CHUNKS; c++) {
            cp_wait3();   // stream chunk for c complete
            const float* stage = xbuf + (c & (NSTAGE - 1)) * STAGE_FLOATS;

            float xs[TGRP][4];
            #pragma unroll
            for (int t = 0; t < TGRP; t++) {
                float4 v = *reinterpret_cast<const float4*>(stage + t * 128 + lane * 4);
                xs[t][0] = v.x; xs[t][1] = v.y; xs[t][2] = v.z; xs[t][3] = v.w;
            }

            // W rows for this lane's 4 d-values (swizzled 16B slots).
            const char* wbase =
                reinterpret_cast<const char*>(ws2) + c * 4096 + lane * 128;
            #pragma unroll
            for (int dd = 0; dd < 4; dd++) {
                ulonglong2 wva = *reinterpret_cast<const ulonglong2*>(
                    wbase + (((dd * 2 + 0) ^ sw) << 4));   // epairs 0,1
                ulonglong2 wvb = *reinterpret_cast<const ulonglong2*>(
                    wbase + (((dd * 2 + 1) ^ sw) << 4));   // epairs 2,3
                #pragma unroll
                for (int t = 0; t < TGRP; t++) {
                    const u64 xd = dup2(xs[t][dd]);
                    ffma2(acc[t][0], xd, wva.x);
                    ffma2(acc[t][1], xd, wva.y);
                    ffma2(acc[t][2], xd, wvb.x);
                    ffma2(acc[t][3], xd, wvb.y);
                }
            }

            // Continuous refill: chunk c+4 of the stream (next group's rows
            // once past the tail) -> DRAM stays busy through the epilogue.
            const uint32_t sdst =
                xbuf_u32 + ((c & (NSTAGE - 1)) * STAGE_FLOATS) * 4;
            if (c < CHUNKS - NSTAGE) {
                #pragma unroll
                for (int t = 0; t < TGRP; t++)
                    cp_async16(sdst + t * 128 * 4,
                               xp + (size_t)t * DDIM + (c + NSTAGE) * 128);
            } else if (has_next) {
                #pragma unroll
                for (int t = 0; t < TGRP; t++)
                    cp_async16(sdst + t * 128 * 4,
                               xp_n + (size_t)t * DDIM + (c - (CHUNKS - NSTAGE)) * 128);
            }
            cp_commit();
        }

        // ---- Epilogue (next group's loads already in flight) ----
        // Unpack f32x2 pairs, then 31-shfl tree reduction: lane v ends with
        // logit(token tok0 + (v>>3), expert v&7).
        float val[32];
        #pragma unroll
        for (int t = 0; t < TGRP; t++)
            #pragma unroll
            for (int p = 0; p < 4; p++) {
                float lo, hi;
                asm("mov.b64 {%0,%1}, %2;" : "=f"(lo), "=f"(hi) : "l"(acc[t][p]));
                val[t * NEXP + p * 2]     = lo;
                val[t * NEXP + p * 2 + 1] = hi;
            }

        #pragma unroll
        for (int i = 0; i < 5; i++) {
            const int off = 16 >> i;
            const int n   = 16 >> i;
            const bool up = (lane & off) != 0;
            #pragma unroll
            for (int j = 0; j < n; j++) {
                float keep = up ? val[j + n] : val[j];
                float send = up ? val[j]     : val[j + n];
                float recv = __shfl_xor_sync(0xffffffffu, send, off);
                val[j] = keep + recv;
            }
        }
        const float logit = val[0];

        // Coalesced logits store: 32 contiguous floats, one per lane.
        out_logits[(size_t)tok0 * NEXP + lane] = logit;

        // Gather this token's 8 logits (token = lane & 3 for lanes 0..3).
        float le[NEXP];
        const int tsel = lane & 3;
        #pragma unroll
        for (int e = 0; e < NEXP; e++)
            le[e] = __shfl_sync(0xffffffffu, logit, tsel * NEXP + e);

        if (lane < TGRP) {
            const int tok = tok0 + lane;

            // top-2 (ties -> lower index, matching jax.lax.top_k)
            int i0 = 0; float v0 = le[0];
            #pragma unroll
            for (int e = 1; e < NEXP; e++)
                if (le[e] > v0) { v0 = le[e]; i0 = e; }
            int i1 = -1; float v1 = -INFINITY;
            #pragma unroll
            for (int e = 0; e < NEXP; e++)
                if (e != i0 && le[e] > v1) { v1 = le[e]; i1 = e; }

            // softmax over [v0, v1] with v0 = max
            float ex = __expf(v1 - v0);
            float g0 = 1.0f / (1.0f + ex);
            float g1 = ex * g0;

            *reinterpret_cast<float2*>(out_idx  + (size_t)tok * 2) =
                make_float2((float)i0, (float)i1);
            *reinterpret_cast<float2*>(out_gate + (size_t)tok * 2) =
                make_float2(g0, g1);
        }
    }
}

extern "C" void kernel_launch(void* const* d_in, const int* in_sizes, int n_in,
                              void* d_out, int out_size)
{
    const float* x = (const float*)d_in[0];
    const float* w = (const float*)d_in[1];
    float* out = (float*)d_out;

    const int n_tokens = in_sizes[0] / DDIM;     // 16384
    const int groups   = n_tokens / TGRP;        // 4096

    cudaFuncSetAttribute(router_kernel,
                         cudaFuncAttributeMaxDynamicSharedMemorySize,
                         SMEM_BYTES);

    router_kernel<<<NBLOCK, THREADS, SMEM_BYTES>>>(x, w, out, n_tokens, groups);
}